// round 5
// baseline (speedup 1.0000x reference)
#include <cuda_runtime.h>
#include <math.h>

// Problem constants
#define NPTS   1048576
#define DH     256        // mlp_x hidden
#define R      64         // Tucker rank (all three)
#define HQ     128
#define HC     128
#define CIN    64
#define CORE_ELEMS (R*R*R)   // 262144
#define NG     32            // quad point-groups per axis (32 pts each)

// ---------------- scratch (device globals) -------------
__device__ float g_up[2][NG][HQ];     // partial u sums per (axis, group)
__device__ float g_syp[2][NG];        // partial sum(y)
__device__ float g_h[HC];             // core hidden tanh
__device__ float g_v[R];              // Tucker-contracted vector (atomic acc)

// ---------------- math helpers -------------
__device__ __forceinline__ float tanh_acc(float x) {
    float e, r;
    asm("ex2.approx.f32 %0, %1;" : "=f"(e) : "f"(x * 2.8853900817779268f));
    asm("rcp.approx.f32 %0, %1;" : "=f"(r) : "f"(e + 1.0f));
    return fmaf(-2.0f, r, 1.0f);
}
__device__ __forceinline__ unsigned long long fma2(unsigned long long a,
                                                   unsigned long long b,
                                                   unsigned long long c) {
    unsigned long long d;
    asm("fma.rn.f32x2 %0, %1, %2, %3;" : "=l"(d) : "l"(a), "l"(b), "l"(c));
    return d;
}
__device__ __forceinline__ unsigned long long packf2(float lo, float hi) {
    unsigned long long d;
    asm("mov.b64 %0, {%1, %2};" : "=l"(d) : "f"(lo), "f"(hi));
    return d;
}
// f32x2 z -> f16x2 tanh(z)
__device__ __forceinline__ unsigned tanh2h(unsigned long long z) {
    float zl, zh; unsigned hp;
    asm("mov.b64 {%0, %1}, %2;" : "=f"(zl), "=f"(zh) : "l"(z));
    asm("cvt.rn.f16x2.f32 %0, %1, %2;" : "=r"(hp) : "f"(zh), "f"(zl));
    asm("tanh.approx.f16x2 %0, %1;" : "=r"(hp) : "r"(hp));
    return hp;
}
__device__ __forceinline__ unsigned hfma2(unsigned a, unsigned b, unsigned c) {
    unsigned d;
    asm("fma.rn.f16x2 %0, %1, %2, %3;" : "=r"(d) : "r"(a), "r"(b), "r"(c));
    return d;
}
__device__ __forceinline__ void unpackh2(unsigned p, float& lo, float& hi) {
    asm("{ .reg .b16 l, h;\n\t"
        "  mov.b32 {l, h}, %2;\n\t"
        "  cvt.f32.f16 %0, l;\n\t"
        "  cvt.f32.f16 %1, h; }\n" : "=f"(lo), "=f"(hi) : "r"(p));
}
__device__ __forceinline__ unsigned bcast_h2(float x) {
    unsigned d;
    asm("{ .reg .b16 h;\n\t"
        "  cvt.rn.f16.f32 h, %1;\n\t"
        "  mov.b32 %0, {h, h}; }\n" : "=r"(d) : "f"(x));
    return d;
}

// ---------------- kZ: zero the atomic accumulator -------------
__global__ void kZ() {
    if (threadIdx.x < R) g_v[threadIdx.x] = 0.f;
}

// ---------------- kH: core hidden tanh -------------
__global__ void __launch_bounds__(128) kH(
    const float* __restrict__ ci, const float* __restrict__ Wc1,
    const float* __restrict__ bc1)
{
    int t = threadIdx.x;
    float z = bc1[t];
    #pragma unroll 8
    for (int i = 0; i < CIN; i++) z = fmaf(ci[i], Wc1[i * HC + t], z);
    g_h[t] = tanh_acc(z);
}

// ---------------- K1: quad partial sums -------------
// grid: 64 blocks x 256. (axis = b>>5, group = b&31, 32 pts)
__global__ void __launch_bounds__(256) k1(
    const float* __restrict__ qx0, const float* __restrict__ qx1,
    const float* __restrict__ eqp,
    const float* __restrict__ Wq01, const float* __restrict__ bq01,
    const float* __restrict__ Wq11, const float* __restrict__ bq11)
{
    int b = blockIdx.x;
    int t = threadIdx.x;

    int ax = b >> 5, g = b & 31;
    const float* qx = ax ? qx1 : qx0;
    const float* Wq = ax ? Wq11 : Wq01;
    const float* bq = ax ? bq11 : bq01;

    __shared__ float sx[32], sy[32], red[256];

    if (t < 32) {
        float x = qx[g * 32 + t];
        float y = sinf(3.14159265358979323846f * eqp[0] * x);
        sx[t] = x; sy[t] = y;
    }
    __syncthreads();

    int k = t & 127, sub = t >> 7;
    float W = Wq[k], bb = bq[k];
    float acc = 0.f;
    int c0 = sub * 16;
    #pragma unroll
    for (int c = 0; c < 16; c++) {
        float z = fmaf(sx[c0 + c], W, bb);
        acc = fmaf(sy[c0 + c], tanh_acc(z), acc);
    }
    red[t] = acc;
    __syncthreads();

    if (t < 128) g_up[ax][g][t] = red[t] + red[t + 128];
    else if (t < 160) {
        float s = sy[t - 128];
        #pragma unroll
        for (int o = 16; o; o >>= 1) s += __shfl_xor_sync(0xffffffffu, s, o);
        if (t == 128) g_syp[ax][g] = s;
    }
}

// ---------------- K2: fused w12 prologue + Wc2 streaming dots + weighted atomic v ----
__global__ void __launch_bounds__(256) k2(
    const float* __restrict__ Wc2, const float* __restrict__ bc2,
    const float* __restrict__ Wq02, const float* __restrict__ bq02,
    const float* __restrict__ Wq12, const float* __restrict__ bq12)
{
    __shared__ float su[2][HQ];
    __shared__ float s12[128];
    __shared__ float ssy[2];
    __shared__ __align__(16) float sw[R * R];   // 16 KB: w12
    __shared__ float sred[8][8];

    int t = threadIdx.x;
    int h = blockIdx.x, ga = blockIdx.y;

    {
        int ax = t >> 7, k = t & 127;
        float s = 0.f;
        #pragma unroll 8
        for (int g = 0; g < NG; g++) s += g_up[ax][g][k];
        su[ax][k] = s;
    }
    if (t < 2) {
        float s = 0.f;
        #pragma unroll 8
        for (int g = 0; g < NG; g++) s += g_syp[t][g];
        ssy[t] = s;
    }
    __syncthreads();

    if (t < 128) {
        int ax = t >> 6, j = t & 63;
        const float* W2 = ax ? Wq12 : Wq02;
        const float* b2 = ax ? bq12 : bq02;
        float s = ssy[ax] * b2[j];
        #pragma unroll 8
        for (int k = 0; k < HQ; k++) s = fmaf(su[ax][k], W2[k * R + j], s);
        s12[t] = s;
    }
    __syncthreads();

    for (int i = t; i < R * R; i += 256)
        sw[i] = s12[i >> 6] * s12[64 + (i & 63)];
    __syncthreads();

    const float* row = (h < HC) ? (Wc2 + (size_t)h * CORE_ELEMS) : bc2;
    const float4* sw4 = (const float4*)sw;

    float acc[8];
    #pragma unroll
    for (int aa = 0; aa < 8; aa++) {
        int a = ga * 8 + aa;
        const float4* p = (const float4*)(row + (size_t)a * (R * R));
        float s = 0.f;
        #pragma unroll
        for (int i = 0; i < 4; i++) {
            float4 c  = p[t + i * 256];
            float4 ww = sw4[t + i * 256];
            s = fmaf(c.x, ww.x, fmaf(c.y, ww.y, fmaf(c.z, ww.z, fmaf(c.w, ww.w, s))));
        }
        acc[aa] = s;
    }

    #pragma unroll
    for (int aa = 0; aa < 8; aa++) {
        float s = acc[aa];
        #pragma unroll
        for (int o = 16; o; o >>= 1) s += __shfl_xor_sync(0xffffffffu, s, o);
        if ((t & 31) == 0) sred[aa][t >> 5] = s;
    }
    __syncthreads();
    if (t < 8) {
        float wh = (h < HC) ? g_h[h] : 1.0f;
        float s = 0.f;
        #pragma unroll
        for (int w = 0; w < 8; w++) s += sred[t][w];
        atomicAdd(&g_v[ga * 8 + t], wh * s);
    }
}

// ---------------- K3 halves: h in [H0, H0+128) -------------
// ADD=false: out[i] = acc*inv         (first half)
// ADD=true : out[i] += acc*inv + cc   (second half, adds constant)
#define PPT 10
#define NPR (PPT/2)
#define HHALF 128
template<int H0, bool ADD>
__global__ void __launch_bounds__(256) k3h(
    const float2* __restrict__ inp,
    const float* __restrict__ Wx1, const float* __restrict__ bx1,
    const float* __restrict__ Wx2, const float* __restrict__ bx2,
    float* __restrict__ out, int n)
{
    __shared__ __align__(16) ulonglong2 swA[HHALF];         // {w0pair, w1pair} f32x2
    __shared__ __align__(16) unsigned long long swB[HHALF]; // bpair f32x2
    __shared__ unsigned swC[HHALF];                          // w2v*scale f16x2 {w,w}
    __shared__ __align__(16) float sv[R];
    __shared__ float smax[4];
    __shared__ float scc;
    int t = threadIdx.x;

    if (t < R) sv[t] = g_v[t];
    __syncthreads();

    // threads 0..127 compute w2v for h = H0 + t
    if (t < HHALF) {
        int h = H0 + t;
        float w2v = 0.f;
        const float4* wrow = (const float4*)(Wx2 + h * R);
        const float4* v4   = (const float4*)sv;
        #pragma unroll
        for (int a = 0; a < R / 4; a++) {
            float4 w = wrow[a], v = v4[a];
            w2v = fmaf(w.x, v.x, fmaf(w.y, v.y, fmaf(w.z, v.z, fmaf(w.w, v.w, w2v))));
        }
        // warp max |w2v| over the 4 active warps
        float m = fabsf(w2v);
        #pragma unroll
        for (int o = 16; o; o >>= 1) m = fmaxf(m, __shfl_xor_sync(0xffffffffu, m, o));
        if ((t & 31) == 0) smax[t >> 5] = m;

        float w0 = Wx1[h], w1 = Wx1[DH + h], bb = bx1[h];
        swA[t] = make_ulonglong2(packf2(w0, w0), packf2(w1, w1));
        swB[t] = packf2(bb, bb);
        // stash raw w2v temporarily in swC slot via shared float reuse:
        ((float*)swC)[t] = w2v;
    }
    if (ADD && t == 0) {
        const float4* brow = (const float4*)bx2;
        const float4* v4   = (const float4*)sv;
        float c = 0.f;
        #pragma unroll
        for (int a = 0; a < R / 4; a++) {
            float4 b = brow[a], v = v4[a];
            c = fmaf(b.x, v.x, fmaf(b.y, v.y, fmaf(b.z, v.z, fmaf(b.w, v.w, c))));
        }
        scc = c;
    }
    __syncthreads();

    float mx = fmaxf(fmaxf(smax[0], smax[1]), fmaxf(smax[2], smax[3]));
    float scale = 1.f, inv = 1.f;
    if (mx > 0.f) {
        int e; frexpf(mx, &e);
        scale = exp2f((float)(2 - e));       // scaled max in [2,4)
        inv   = exp2f((float)(e - 2));
    }
    float cc = ADD ? scc : 0.f;
    __syncthreads();
    if (t < HHALF) {
        float w2v = ((float*)swC)[t];
        __syncthreads();
        swC[t] = bcast_h2(w2v * scale);
    } else {
        __syncthreads();
    }
    __syncthreads();

    int base = blockIdx.x * (256 * PPT) + t;

    unsigned long long X0[NPR], X1[NPR];
    float aLo[NPR], aHi[NPR];
    #pragma unroll
    for (int pr = 0; pr < NPR; pr++) {
        int i0 = base + (2 * pr) * 256;
        int i1 = base + (2 * pr + 1) * 256;
        float2 a = (i0 < n) ? inp[i0] : make_float2(0.f, 0.f);
        float2 b = (i1 < n) ? inp[i1] : make_float2(0.f, 0.f);
        X0[pr] = packf2(a.x, b.x);
        X1[pr] = packf2(a.y, b.y);
        aLo[pr] = 0.f; aHi[pr] = 0.f;
    }

    for (int hb = 0; hb < HHALF; hb += 4) {      // flush every 4 h for precision
        unsigned a16[NPR];
        #pragma unroll
        for (int pr = 0; pr < NPR; pr++) a16[pr] = 0u;

        #pragma unroll
        for (int hh = 0; hh < 4; hh++) {
            int h = hb + hh;
            ulonglong2 wz = swA[h];
            unsigned long long bp = swB[h];
            unsigned wv = swC[h];
            #pragma unroll
            for (int pr = 0; pr < NPR; pr++) {
                unsigned long long z = fma2(X0[pr], wz.x, fma2(X1[pr], wz.y, bp));
                a16[pr] = hfma2(tanh2h(z), wv, a16[pr]);
            }
        }
        #pragma unroll
        for (int pr = 0; pr < NPR; pr++) {
            float lo, hi;
            unpackh2(a16[pr], lo, hi);
            aLo[pr] += lo; aHi[pr] += hi;
        }
    }

    #pragma unroll
    for (int pr = 0; pr < NPR; pr++) {
        int i0 = base + (2 * pr) * 256;
        int i1 = base + (2 * pr + 1) * 256;
        if (ADD) {
            if (i0 < n) out[i0] += fmaf(aLo[pr], inv, cc);
            if (i1 < n) out[i1] += fmaf(aHi[pr], inv, cc);
        } else {
            if (i0 < n) out[i0] = aLo[pr] * inv;
            if (i1 < n) out[i1] = aHi[pr] * inv;
        }
    }
}

// ---------------- launch -------------
extern "C" void kernel_launch(void* const* d_in, const int* in_sizes, int n_in,
                              void* d_out, int out_size)
{
    const float* input  = (const float*)d_in[0];
    const float* eqp    = (const float*)d_in[1];
    const float* qx0    = (const float*)d_in[2];
    const float* qx1    = (const float*)d_in[3];
    const float* ci     = (const float*)d_in[4];
    const float* Wx1    = (const float*)d_in[5];
    const float* bx1    = (const float*)d_in[6];
    const float* Wx2    = (const float*)d_in[7];
    const float* bx2    = (const float*)d_in[8];
    const float* Wq01   = (const float*)d_in[9];
    const float* bq01   = (const float*)d_in[10];
    const float* Wq02   = (const float*)d_in[11];
    const float* bq02   = (const float*)d_in[12];
    const float* Wq11   = (const float*)d_in[13];
    const float* bq11   = (const float*)d_in[14];
    const float* Wq12   = (const float*)d_in[15];
    const float* bq12   = (const float*)d_in[16];
    const float* Wc1    = (const float*)d_in[17];
    const float* bc1    = (const float*)d_in[18];
    const float* Wc2    = (const float*)d_in[19];
    const float* bc2    = (const float*)d_in[20];

    int n = in_sizes[0] / 2;

    kZ <<<1, 64>>>();
    kH <<<1, 128>>>(ci, Wc1, bc1);
    k1 <<<64, 256>>>(qx0, qx1, eqp, Wq01, bq01, Wq11, bq11);
    k2 <<<dim3(129, 8), 256>>>(Wc2, bc2, Wq02, bq02, Wq12, bq12);

    int blocks = (n + 256 * PPT - 1) / (256 * PPT);
    if (blocks < 444) blocks = 444;
    k3h<0,   false><<<blocks, 256>>>((const float2*)input, Wx1, bx1, Wx2, bx2, (float*)d_out, n);
    k3h<128, true ><<<blocks, 256>>>((const float2*)input, Wx1, bx1, Wx2, bx2, (float*)d_out, n);
}

// round 6
// speedup vs baseline: 1.1764x; 1.1764x over previous
#include <cuda_runtime.h>
#include <math.h>

// Problem constants
#define NPTS   1048576
#define DH     256        // mlp_x hidden
#define R      64         // Tucker rank (all three)
#define HQ     128
#define HC     128
#define CIN    64
#define CORE_ELEMS (R*R*R)   // 262144
#define NG     32            // quad point-groups per axis (32 pts each)

// ---------------- scratch (device globals) -------------
__device__ float g_up[2][NG][HQ];     // partial u sums per (axis, group)
__device__ float g_syp[2][NG];        // partial sum(y)
__device__ float g_h[HC];             // core hidden tanh
__device__ float g_v[R];              // Tucker-contracted vector (atomic acc)
__device__ __align__(16) float g_w12[R * R];   // s1 outer s2 (computed once)

// ---------------- math helpers -------------
__device__ __forceinline__ float tanh_acc(float x) {
    float e, r;
    asm("ex2.approx.f32 %0, %1;" : "=f"(e) : "f"(x * 2.8853900817779268f));
    asm("rcp.approx.f32 %0, %1;" : "=f"(r) : "f"(e + 1.0f));
    return fmaf(-2.0f, r, 1.0f);
}
__device__ __forceinline__ unsigned long long fma2(unsigned long long a,
                                                   unsigned long long b,
                                                   unsigned long long c) {
    unsigned long long d;
    asm("fma.rn.f32x2 %0, %1, %2, %3;" : "=l"(d) : "l"(a), "l"(b), "l"(c));
    return d;
}
__device__ __forceinline__ unsigned long long packf2(float lo, float hi) {
    unsigned long long d;
    asm("mov.b64 %0, {%1, %2};" : "=l"(d) : "f"(lo), "f"(hi));
    return d;
}
__device__ __forceinline__ unsigned tanh2h(unsigned long long z) {
    float zl, zh; unsigned hp;
    asm("mov.b64 {%0, %1}, %2;" : "=f"(zl), "=f"(zh) : "l"(z));
    asm("cvt.rn.f16x2.f32 %0, %1, %2;" : "=r"(hp) : "f"(zh), "f"(zl));
    asm("tanh.approx.f16x2 %0, %1;" : "=r"(hp) : "r"(hp));
    return hp;
}
__device__ __forceinline__ unsigned hfma2(unsigned a, unsigned b, unsigned c) {
    unsigned d;
    asm("fma.rn.f16x2 %0, %1, %2, %3;" : "=r"(d) : "r"(a), "r"(b), "r"(c));
    return d;
}
__device__ __forceinline__ void unpackh2(unsigned p, float& lo, float& hi) {
    asm("{ .reg .b16 l, h;\n\t"
        "  mov.b32 {l, h}, %2;\n\t"
        "  cvt.f32.f16 %0, l;\n\t"
        "  cvt.f32.f16 %1, h; }\n" : "=f"(lo), "=f"(hi) : "r"(p));
}
__device__ __forceinline__ unsigned bcast_h2(float x) {
    unsigned d;
    asm("{ .reg .b16 h;\n\t"
        "  cvt.rn.f16.f32 h, %1;\n\t"
        "  mov.b32 %0, {h, h}; }\n" : "=r"(d) : "f"(x));
    return d;
}

// ---------------- K1: quad partial sums + aux (core hidden, zero g_v) -------------
// grid: 65 blocks x 256. blocks 0..63: (axis = b>>5, group = b&31); block 64: aux.
__global__ void __launch_bounds__(256) k1(
    const float* __restrict__ qx0, const float* __restrict__ qx1,
    const float* __restrict__ eqp,
    const float* __restrict__ Wq01, const float* __restrict__ bq01,
    const float* __restrict__ Wq11, const float* __restrict__ bq11,
    const float* __restrict__ ci,   const float* __restrict__ Wc1,
    const float* __restrict__ bc1)
{
    int b = blockIdx.x;
    int t = threadIdx.x;

    if (b == 64) {
        if (t < R) g_v[t] = 0.f;
        if (t < HC) {
            float z = bc1[t];
            #pragma unroll 8
            for (int i = 0; i < CIN; i++) z = fmaf(ci[i], Wc1[i * HC + t], z);
            g_h[t] = tanh_acc(z);
        }
        return;
    }

    int ax = b >> 5, g = b & 31;
    const float* qx = ax ? qx1 : qx0;
    const float* Wq = ax ? Wq11 : Wq01;
    const float* bq = ax ? bq11 : bq01;

    __shared__ float sx[32], sy[32], red[256];

    if (t < 32) {
        float x = qx[g * 32 + t];
        float y = sinf(3.14159265358979323846f * eqp[0] * x);
        sx[t] = x; sy[t] = y;
    }
    __syncthreads();

    int k = t & 127, sub = t >> 7;
    float W = Wq[k], bb = bq[k];
    float acc = 0.f;
    int c0 = sub * 16;
    #pragma unroll
    for (int c = 0; c < 16; c++) {
        float z = fmaf(sx[c0 + c], W, bb);
        acc = fmaf(sy[c0 + c], tanh_acc(z), acc);
    }
    red[t] = acc;
    __syncthreads();

    if (t < 128) g_up[ax][g][t] = red[t] + red[t + 128];
    else if (t < 160) {
        float s = sy[t - 128];
        #pragma unroll
        for (int o = 16; o; o >>= 1) s += __shfl_xor_sync(0xffffffffu, s, o);
        if (t == 128) g_syp[ax][g] = s;
    }
}

// ---------------- K1b: compute w12 ONCE -> g_w12 -------------
__global__ void __launch_bounds__(256) k1b(
    const float* __restrict__ Wq02, const float* __restrict__ bq02,
    const float* __restrict__ Wq12, const float* __restrict__ bq12)
{
    __shared__ float su[2][HQ];
    __shared__ float s12[128];
    __shared__ float ssy[2];
    int t = threadIdx.x;

    {   // reduce partial u over 32 groups
        int ax = t >> 7, k = t & 127;
        float s0 = 0.f, s1 = 0.f, s2 = 0.f, s3 = 0.f;
        #pragma unroll
        for (int g = 0; g < NG; g += 4) {
            s0 += g_up[ax][g + 0][k];
            s1 += g_up[ax][g + 1][k];
            s2 += g_up[ax][g + 2][k];
            s3 += g_up[ax][g + 3][k];
        }
        su[ax][k] = (s0 + s1) + (s2 + s3);
    }
    if (t < 2) {
        float s = 0.f;
        #pragma unroll
        for (int g = 0; g < NG; g++) s += g_syp[t][g];
        ssy[t] = s;
    }
    __syncthreads();

    // s12[j]: 128 outputs, 2 threads each (64 k's per thread)
    {
        int j = t & 127, sub = t >> 7;
        int ax = j >> 6, jj = j & 63;
        const float* W2 = ax ? Wq12 : Wq02;   // (128,64) row-major
        const float* b2 = ax ? bq12 : bq02;
        float s = sub ? 0.f : ssy[ax] * b2[jj];
        int k0 = sub * 64;
        #pragma unroll 8
        for (int k = 0; k < 64; k++) s = fmaf(su[ax][k0 + k], W2[(k0 + k) * R + jj], s);
        // combine the two halves via shared
        __shared__ float part[256];
        part[t] = s;
        __syncthreads();
        if (t < 128) s12[t] = part[t] + part[t + 128];
    }
    __syncthreads();

    #pragma unroll
    for (int i = t; i < R * R; i += 256)
        g_w12[i] = s12[i >> 6] * s12[64 + (i & 63)];
}

// ---------------- K2: pure streaming GEMV vs w12, weighted atomic into v ----
// grid: (129, 8) x 256. h=128 row is bc2 (weight 1.0). Each block: 8 a's, 128KB.
__global__ void __launch_bounds__(256) k2(
    const float* __restrict__ Wc2, const float* __restrict__ bc2)
{
    __shared__ __align__(16) float sw[R * R];   // 16 KB: w12
    __shared__ float sred[8][8];
    int t = threadIdx.x;
    int h = blockIdx.x, ga = blockIdx.y;

    // fast prologue: copy w12 from L2
    {
        const float4* src = (const float4*)g_w12;
        float4* dst = (float4*)sw;
        #pragma unroll
        for (int i = 0; i < 4; i++) dst[t + i * 256] = src[t + i * 256];
    }
    __syncthreads();

    const float* row  = (h < HC) ? (Wc2 + (size_t)h * CORE_ELEMS) : bc2;
    const float* base = row + (size_t)ga * 8 * (R * R);   // 8 a's of 4096 floats
    const float4* sw4 = (const float4*)sw;

    float acc[8] = {0.f, 0.f, 0.f, 0.f, 0.f, 0.f, 0.f, 0.f};

    #pragma unroll
    for (int i = 0; i < 4; i++) {
        float4 c[8];
        const float4* p = (const float4*)base + t + i * 256;
        #pragma unroll
        for (int aa = 0; aa < 8; aa++)           // 8 batched independent LDG.128
            c[aa] = p[aa * 1024];                // +aa*4096 floats (imm offsets)
        float4 ww = sw4[t + i * 256];
        #pragma unroll
        for (int aa = 0; aa < 8; aa++)
            acc[aa] += fmaf(c[aa].x, ww.x, fmaf(c[aa].y, ww.y,
                       fmaf(c[aa].z, ww.z, c[aa].w * ww.w)));
    }

    #pragma unroll
    for (int aa = 0; aa < 8; aa++) {
        float s = acc[aa];
        #pragma unroll
        for (int o = 16; o; o >>= 1) s += __shfl_xor_sync(0xffffffffu, s, o);
        if ((t & 31) == 0) sred[aa][t >> 5] = s;
    }
    __syncthreads();
    if (t < 8) {
        float wh = (h < HC) ? g_h[h] : 1.0f;
        float s = 0.f;
        #pragma unroll
        for (int w = 0; w < 8; w++) s += sred[t][w];
        atomicAdd(&g_v[ga * 8 + t], wh * s);
    }
}

// ---------------- K3: w2v preamble (+range scaling) + f16x2 MAC main loop -------------
#define PPT 10
#define NPR (PPT/2)
__global__ void __launch_bounds__(256) k3(
    const float2* __restrict__ inp,
    const float* __restrict__ Wx1, const float* __restrict__ bx1,
    const float* __restrict__ Wx2, const float* __restrict__ bx2,
    float* __restrict__ out, int n)
{
    __shared__ __align__(16) ulonglong2 swA[DH];         // {w0pair, w1pair} f32x2
    __shared__ __align__(16) unsigned long long swB[DH]; // bpair f32x2
    __shared__ unsigned swC[DH];                          // w2v*scale f16x2 {w,w}
    __shared__ __align__(16) float sv[R];
    __shared__ float smax[8];
    int t = threadIdx.x;

    if (t < R) sv[t] = g_v[t];
    __syncthreads();

    float w2v = 0.f, cc = 0.f;
    {
        const float4* wrow = (const float4*)(Wx2 + t * R);
        const float4* brow = (const float4*)bx2;
        const float4* v4   = (const float4*)sv;
        #pragma unroll
        for (int a = 0; a < R / 4; a++) {
            float4 w = wrow[a], b = brow[a], v = v4[a];
            w2v = fmaf(w.x, v.x, fmaf(w.y, v.y, fmaf(w.z, v.z, fmaf(w.w, v.w, w2v))));
            cc  = fmaf(b.x, v.x, fmaf(b.y, v.y, fmaf(b.z, v.z, fmaf(b.w, v.w, cc))));
        }
    }

    {
        float m = fabsf(w2v);
        #pragma unroll
        for (int o = 16; o; o >>= 1) m = fmaxf(m, __shfl_xor_sync(0xffffffffu, m, o));
        if ((t & 31) == 0) smax[t >> 5] = m;
    }
    __syncthreads();
    float mx = smax[0];
    #pragma unroll
    for (int w = 1; w < 8; w++) mx = fmaxf(mx, smax[w]);

    float scale = 1.f, inv = 1.f;
    if (mx > 0.f) {
        int e; frexpf(mx, &e);
        scale = exp2f((float)(2 - e));       // scaled max in [2,4)
        inv   = exp2f((float)(e - 2));
    }

    {
        float w0 = Wx1[t], w1 = Wx1[DH + t], bb = bx1[t];
        swA[t] = make_ulonglong2(packf2(w0, w0), packf2(w1, w1));
        swB[t] = packf2(bb, bb);
        swC[t] = bcast_h2(w2v * scale);
    }
    __syncthreads();

    int base = blockIdx.x * (256 * PPT) + t;

    unsigned long long X0[NPR], X1[NPR];
    float aLo[NPR], aHi[NPR];
    #pragma unroll
    for (int pr = 0; pr < NPR; pr++) {
        int i0 = base + (2 * pr) * 256;
        int i1 = base + (2 * pr + 1) * 256;
        float2 a = (i0 < n) ? inp[i0] : make_float2(0.f, 0.f);
        float2 b = (i1 < n) ? inp[i1] : make_float2(0.f, 0.f);
        X0[pr] = packf2(a.x, b.x);
        X1[pr] = packf2(a.y, b.y);
        aLo[pr] = 0.f; aHi[pr] = 0.f;
    }

    for (int hb = 0; hb < DH; hb += 4) {     // flush every 4 h for precision
        unsigned a16[NPR];
        #pragma unroll
        for (int pr = 0; pr < NPR; pr++) a16[pr] = 0u;

        #pragma unroll
        for (int hh = 0; hh < 4; hh++) {
            int h = hb + hh;
            ulonglong2 wz = swA[h];
            unsigned long long bp = swB[h];
            unsigned wv = swC[h];
            #pragma unroll
            for (int pr = 0; pr < NPR; pr++) {
                unsigned long long z = fma2(X0[pr], wz.x, fma2(X1[pr], wz.y, bp));
                a16[pr] = hfma2(tanh2h(z), wv, a16[pr]);
            }
        }
        #pragma unroll
        for (int pr = 0; pr < NPR; pr++) {
            float lo, hi;
            unpackh2(a16[pr], lo, hi);
            aLo[pr] += lo; aHi[pr] += hi;
        }
    }

    #pragma unroll
    for (int pr = 0; pr < NPR; pr++) {
        int i0 = base + (2 * pr) * 256;
        int i1 = base + (2 * pr + 1) * 256;
        if (i0 < n) out[i0] = fmaf(aLo[pr], inv, cc);
        if (i1 < n) out[i1] = fmaf(aHi[pr], inv, cc);
    }
}

// ---------------- launch -------------
extern "C" void kernel_launch(void* const* d_in, const int* in_sizes, int n_in,
                              void* d_out, int out_size)
{
    const float* input  = (const float*)d_in[0];
    const float* eqp    = (const float*)d_in[1];
    const float* qx0    = (const float*)d_in[2];
    const float* qx1    = (const float*)d_in[3];
    const float* ci     = (const float*)d_in[4];
    const float* Wx1    = (const float*)d_in[5];
    const float* bx1    = (const float*)d_in[6];
    const float* Wx2    = (const float*)d_in[7];
    const float* bx2    = (const float*)d_in[8];
    const float* Wq01   = (const float*)d_in[9];
    const float* bq01   = (const float*)d_in[10];
    const float* Wq02   = (const float*)d_in[11];
    const float* bq02   = (const float*)d_in[12];
    const float* Wq11   = (const float*)d_in[13];
    const float* bq11   = (const float*)d_in[14];
    const float* Wq12   = (const float*)d_in[15];
    const float* bq12   = (const float*)d_in[16];
    const float* Wc1    = (const float*)d_in[17];
    const float* bc1    = (const float*)d_in[18];
    const float* Wc2    = (const float*)d_in[19];
    const float* bc2    = (const float*)d_in[20];

    int n = in_sizes[0] / 2;

    k1 <<<65, 256>>>(qx0, qx1, eqp, Wq01, bq01, Wq11, bq11, ci, Wc1, bc1);
    k1b<<<1, 256>>>(Wq02, bq02, Wq12, bq12);
    k2 <<<dim3(129, 8), 256>>>(Wc2, bc2);

    int blocks = (n + 256 * PPT - 1) / (256 * PPT);
    if (blocks < 444) blocks = 444;
    k3 <<<blocks, 256>>>((const float2*)input, Wx1, bx1, Wx2, bx2, (float*)d_out, n);
}

// round 7
// speedup vs baseline: 1.5053x; 1.2796x over previous
#include <cuda_runtime.h>
#include <math.h>

// Problem constants
#define NPTS   1048576
#define DH     256        // mlp_x hidden
#define R      64         // Tucker rank
#define HQ     128
#define HC     128
#define CIN    64
#define CORE_ELEMS (R*R*R)
#define NG     32            // quad point-groups per axis
#define G      512            // LUT grid per axis
#define GSHIFT 9

// ---------------- scratch (device globals) -------------
__device__ float g_up[2][NG][HQ];
__device__ float g_syp[2][NG];
__device__ float g_h[HC];
__device__ float g_v[R];
__device__ __align__(16) float g_w12[R * R];
__device__ unsigned g_range[4];          // enc(min0), enc(max0), enc(min1), enc(max1)
__device__ __align__(16) float g_tbl[G * G];   // 1 MB LUT

// ---------------- helpers -------------
__device__ __forceinline__ float tanh_acc(float x) {
    float e, r;
    asm("ex2.approx.f32 %0, %1;" : "=f"(e) : "f"(x * 2.8853900817779268f));
    asm("rcp.approx.f32 %0, %1;" : "=f"(r) : "f"(e + 1.0f));
    return fmaf(-2.0f, r, 1.0f);
}
__device__ __forceinline__ float tanh_hw(float x) {
    float y;
    asm("tanh.approx.f32 %0, %1;" : "=f"(y) : "f"(x));
    return y;
}
// monotonic unsigned encoding of float (for atomic min/max)
__device__ __forceinline__ unsigned encf(float f) {
    unsigned u = __float_as_uint(f);
    return (u & 0x80000000u) ? ~u : (u | 0x80000000u);
}
__device__ __forceinline__ float decf(unsigned u) {
    return (u & 0x80000000u) ? __uint_as_float(u ^ 0x80000000u)
                             : __uint_as_float(~u);
}

// ---------------- kZ: init accumulators -------------
__global__ void kZ() {
    int t = threadIdx.x;
    if (t < R) g_v[t] = 0.f;
    if (t == 64) { g_range[0] = 0xFFFFFFFFu; g_range[2] = 0xFFFFFFFFu; }
    if (t == 65) { g_range[1] = 0u;          g_range[3] = 0u; }
}

// ---------------- K1: quad partial sums + aux + input min/max -------------
// blocks 0..63: quad (axis=b>>5, group=b&31); block 64: core hidden; 65..212: range.
__global__ void __launch_bounds__(256) k1(
    const float* __restrict__ qx0, const float* __restrict__ qx1,
    const float* __restrict__ eqp,
    const float* __restrict__ Wq01, const float* __restrict__ bq01,
    const float* __restrict__ Wq11, const float* __restrict__ bq11,
    const float* __restrict__ ci,   const float* __restrict__ Wc1,
    const float* __restrict__ bc1,
    const float4* __restrict__ inp4, int nf4)
{
    int b = blockIdx.x;
    int t = threadIdx.x;

    if (b >= 65) {           // ---- input bounding box ----
        __shared__ float rmin0[8], rmax0[8], rmin1[8], rmax1[8];
        int r = b - 65;
        float m0l = 1e30f, m0h = -1e30f, m1l = 1e30f, m1h = -1e30f;
        for (int i = r * 256 + t; i < nf4; i += 148 * 256) {
            float4 v = inp4[i];
            m0l = fminf(m0l, fminf(v.x, v.z));
            m0h = fmaxf(m0h, fmaxf(v.x, v.z));
            m1l = fminf(m1l, fminf(v.y, v.w));
            m1h = fmaxf(m1h, fmaxf(v.y, v.w));
        }
        #pragma unroll
        for (int o = 16; o; o >>= 1) {
            m0l = fminf(m0l, __shfl_xor_sync(0xffffffffu, m0l, o));
            m0h = fmaxf(m0h, __shfl_xor_sync(0xffffffffu, m0h, o));
            m1l = fminf(m1l, __shfl_xor_sync(0xffffffffu, m1l, o));
            m1h = fmaxf(m1h, __shfl_xor_sync(0xffffffffu, m1h, o));
        }
        if ((t & 31) == 0) {
            int w = t >> 5;
            rmin0[w] = m0l; rmax0[w] = m0h; rmin1[w] = m1l; rmax1[w] = m1h;
        }
        __syncthreads();
        if (t == 0) {
            float a0 = rmin0[0], b0 = rmax0[0], a1 = rmin1[0], b1 = rmax1[0];
            #pragma unroll
            for (int w = 1; w < 8; w++) {
                a0 = fminf(a0, rmin0[w]); b0 = fmaxf(b0, rmax0[w]);
                a1 = fminf(a1, rmin1[w]); b1 = fmaxf(b1, rmax1[w]);
            }
            atomicMin(&g_range[0], encf(a0));
            atomicMax(&g_range[1], encf(b0));
            atomicMin(&g_range[2], encf(a1));
            atomicMax(&g_range[3], encf(b1));
        }
        return;
    }

    if (b == 64) {           // ---- core hidden ----
        if (t < HC) {
            float z = bc1[t];
            #pragma unroll 8
            for (int i = 0; i < CIN; i++) z = fmaf(ci[i], Wc1[i * HC + t], z);
            g_h[t] = tanh_acc(z);
        }
        return;
    }

    int ax = b >> 5, g = b & 31;
    const float* qx = ax ? qx1 : qx0;
    const float* Wq = ax ? Wq11 : Wq01;
    const float* bq = ax ? bq11 : bq01;

    __shared__ float sx[32], sy[32], red[256];

    if (t < 32) {
        float x = qx[g * 32 + t];
        float y = sinf(3.14159265358979323846f * eqp[0] * x);
        sx[t] = x; sy[t] = y;
    }
    __syncthreads();

    int k = t & 127, sub = t >> 7;
    float W = Wq[k], bb = bq[k];
    float acc = 0.f;
    int c0 = sub * 16;
    #pragma unroll
    for (int c = 0; c < 16; c++) {
        float z = fmaf(sx[c0 + c], W, bb);
        acc = fmaf(sy[c0 + c], tanh_acc(z), acc);
    }
    red[t] = acc;
    __syncthreads();

    if (t < 128) g_up[ax][g][t] = red[t] + red[t + 128];
    else if (t < 160) {
        float s = sy[t - 128];
        #pragma unroll
        for (int o = 16; o; o >>= 1) s += __shfl_xor_sync(0xffffffffu, s, o);
        if (t == 128) g_syp[ax][g] = s;
    }
}

// ---------------- K1b: compute w12 ONCE -> g_w12 -------------
__global__ void __launch_bounds__(256) k1b(
    const float* __restrict__ Wq02, const float* __restrict__ bq02,
    const float* __restrict__ Wq12, const float* __restrict__ bq12)
{
    __shared__ float su[2][HQ];
    __shared__ float s12[128];
    __shared__ float ssy[2];
    int t = threadIdx.x;

    {
        int ax = t >> 7, k = t & 127;
        float s0 = 0.f, s1 = 0.f, s2 = 0.f, s3 = 0.f;
        #pragma unroll
        for (int g = 0; g < NG; g += 4) {
            s0 += g_up[ax][g + 0][k];
            s1 += g_up[ax][g + 1][k];
            s2 += g_up[ax][g + 2][k];
            s3 += g_up[ax][g + 3][k];
        }
        su[ax][k] = (s0 + s1) + (s2 + s3);
    }
    if (t < 2) {
        float s = 0.f;
        #pragma unroll
        for (int g = 0; g < NG; g++) s += g_syp[t][g];
        ssy[t] = s;
    }
    __syncthreads();

    {
        int j = t & 127, sub = t >> 7;
        int ax = j >> 6, jj = j & 63;
        const float* W2 = ax ? Wq12 : Wq02;
        const float* b2 = ax ? bq12 : bq02;
        float s = sub ? 0.f : ssy[ax] * b2[jj];
        int k0 = sub * 64;
        #pragma unroll 8
        for (int k = 0; k < 64; k++) s = fmaf(su[ax][k0 + k], W2[(k0 + k) * R + jj], s);
        __shared__ float part[256];
        part[t] = s;
        __syncthreads();
        if (t < 128) s12[t] = part[t] + part[t + 128];
    }
    __syncthreads();

    #pragma unroll
    for (int i = t; i < R * R; i += 256)
        g_w12[i] = s12[i >> 6] * s12[64 + (i & 63)];
}

// ---------------- K2: streaming GEMV vs w12, weighted atomic into v ----
__global__ void __launch_bounds__(256) k2(
    const float* __restrict__ Wc2, const float* __restrict__ bc2)
{
    __shared__ __align__(16) float sw[R * R];
    __shared__ float sred[8][8];
    int t = threadIdx.x;
    int h = blockIdx.x, ga = blockIdx.y;

    {
        const float4* src = (const float4*)g_w12;
        float4* dst = (float4*)sw;
        #pragma unroll
        for (int i = 0; i < 4; i++) dst[t + i * 256] = src[t + i * 256];
    }
    __syncthreads();

    const float* row  = (h < HC) ? (Wc2 + (size_t)h * CORE_ELEMS) : bc2;
    const float* base = row + (size_t)ga * 8 * (R * R);
    const float4* sw4 = (const float4*)sw;

    float acc[8] = {0.f, 0.f, 0.f, 0.f, 0.f, 0.f, 0.f, 0.f};

    #pragma unroll
    for (int i = 0; i < 4; i++) {
        float4 c[8];
        const float4* p = (const float4*)base + t + i * 256;
        #pragma unroll
        for (int aa = 0; aa < 8; aa++)
            c[aa] = p[aa * 1024];
        float4 ww = sw4[t + i * 256];
        #pragma unroll
        for (int aa = 0; aa < 8; aa++)
            acc[aa] += fmaf(c[aa].x, ww.x, fmaf(c[aa].y, ww.y,
                       fmaf(c[aa].z, ww.z, c[aa].w * ww.w)));
    }

    #pragma unroll
    for (int aa = 0; aa < 8; aa++) {
        float s = acc[aa];
        #pragma unroll
        for (int o = 16; o; o >>= 1) s += __shfl_xor_sync(0xffffffffu, s, o);
        if ((t & 31) == 0) sred[aa][t >> 5] = s;
    }
    __syncthreads();
    if (t < 8) {
        float wh = (h < HC) ? g_h[h] : 1.0f;
        float s = 0.f;
        #pragma unroll
        for (int w = 0; w < 8; w++) s += sred[t][w];
        atomicAdd(&g_v[ga * 8 + t], wh * s);
    }
}

// ---------------- kB: build the 512x512 LUT (MUFU-bound) -------------
// tbl[j*G+i] = c + sum_h tanh(w0*x0(i) + w1*x1(j) + b) * w2v[h]
__global__ void __launch_bounds__(256) kB(
    const float* __restrict__ Wx1, const float* __restrict__ bx1,
    const float* __restrict__ Wx2, const float* __restrict__ bx2)
{
    __shared__ __align__(16) float4 sw[DH];   // {w0, w1, b, w2v}
    __shared__ __align__(16) float sv[R];
    int t = threadIdx.x;

    if (t < R) sv[t] = g_v[t];
    __syncthreads();

    float w2v = 0.f, cc = 0.f;
    {
        const float4* wrow = (const float4*)(Wx2 + t * R);
        const float4* brow = (const float4*)bx2;
        const float4* v4   = (const float4*)sv;
        #pragma unroll
        for (int a = 0; a < R / 4; a++) {
            float4 w = wrow[a], b = brow[a], v = v4[a];
            w2v = fmaf(w.x, v.x, fmaf(w.y, v.y, fmaf(w.z, v.z, fmaf(w.w, v.w, w2v))));
            cc  = fmaf(b.x, v.x, fmaf(b.y, v.y, fmaf(b.z, v.z, fmaf(b.w, v.w, cc))));
        }
    }
    sw[t] = make_float4(Wx1[t], Wx1[DH + t], bx1[t], w2v);
    __syncthreads();

    float lo0 = decf(g_range[0]), hi0 = decf(g_range[1]);
    float lo1 = decf(g_range[2]), hi1 = decf(g_range[3]);
    float h0 = (hi0 - lo0) * (1.0f / (G - 1));
    float h1 = (hi1 - lo1) * (1.0f / (G - 1));

    int idx = blockIdx.x * 256 + t;
    int i = idx & (G - 1);
    int j = idx >> GSHIFT;
    float x0 = fmaf((float)i, h0, lo0);
    float x1 = fmaf((float)j, h1, lo1);

    float acc = cc;
    #pragma unroll 8
    for (int h = 0; h < DH; h++) {
        float4 w = sw[h];
        float z = fmaf(x0, w.x, fmaf(x1, w.y, w.z));
        acc = fmaf(tanh_hw(z), w.w, acc);
    }
    g_tbl[idx] = acc;
}

// ---------------- kI: bilinear interpolation of the LUT -------------
#define IPT 4
__global__ void __launch_bounds__(256) kI(
    const float2* __restrict__ inp, float* __restrict__ out, int n)
{
    __shared__ float sr[4];
    int t = threadIdx.x;
    if (t < 4) sr[t] = decf(g_range[t]);
    __syncthreads();
    float lo0 = sr[0], hi0 = sr[1], lo1 = sr[2], hi1 = sr[3];
    float inv0 = (hi0 > lo0) ? (float)(G - 1) / (hi0 - lo0) : 0.f;
    float inv1 = (hi1 > lo1) ? (float)(G - 1) / (hi1 - lo1) : 0.f;

    int base = blockIdx.x * (256 * IPT) + t;

    #pragma unroll
    for (int p = 0; p < IPT; p++) {
        int idx = base + p * 256;
        if (idx >= n) continue;
        float2 xy = inp[idx];
        float u = (xy.x - lo0) * inv0;
        float v = (xy.y - lo1) * inv1;
        int i = __float2int_rd(u);
        int j = __float2int_rd(v);
        i = min(max(i, 0), G - 2);
        j = min(max(j, 0), G - 2);
        float fu = u - (float)i;
        float fv = v - (float)j;
        const float* p0 = g_tbl + j * G + i;
        float t00 = p0[0],     t01 = p0[1];
        float t10 = p0[G],     t11 = p0[G + 1];
        float a = fmaf(fu, t01 - t00, t00);
        float b = fmaf(fu, t11 - t10, t10);
        out[idx] = fmaf(fv, b - a, a);
    }
}

// ---------------- launch -------------
extern "C" void kernel_launch(void* const* d_in, const int* in_sizes, int n_in,
                              void* d_out, int out_size)
{
    const float* input  = (const float*)d_in[0];
    const float* eqp    = (const float*)d_in[1];
    const float* qx0    = (const float*)d_in[2];
    const float* qx1    = (const float*)d_in[3];
    const float* ci     = (const float*)d_in[4];
    const float* Wx1    = (const float*)d_in[5];
    const float* bx1    = (const float*)d_in[6];
    const float* Wx2    = (const float*)d_in[7];
    const float* bx2    = (const float*)d_in[8];
    const float* Wq01   = (const float*)d_in[9];
    const float* bq01   = (const float*)d_in[10];
    const float* Wq02   = (const float*)d_in[11];
    const float* bq02   = (const float*)d_in[12];
    const float* Wq11   = (const float*)d_in[13];
    const float* bq11   = (const float*)d_in[14];
    const float* Wq12   = (const float*)d_in[15];
    const float* bq12   = (const float*)d_in[16];
    const float* Wc1    = (const float*)d_in[17];
    const float* bc1    = (const float*)d_in[18];
    const float* Wc2    = (const float*)d_in[19];
    const float* bc2    = (const float*)d_in[20];

    int n = in_sizes[0] / 2;
    int nf4 = in_sizes[0] / 4;

    kZ <<<1, 128>>>();
    k1 <<<213, 256>>>(qx0, qx1, eqp, Wq01, bq01, Wq11, bq11, ci, Wc1, bc1,
                      (const float4*)input, nf4);
    k1b<<<1, 256>>>(Wq02, bq02, Wq12, bq12);
    k2 <<<dim3(129, 8), 256>>>(Wc2, bc2);
    kB <<<G * G / 256, 256>>>(Wx1, bx1, Wx2, bx2);
    kI <<<(n + 256 * IPT - 1) / (256 * IPT), 256>>>((const float2*)input, (float*)d_out, n);
}

// round 8
// speedup vs baseline: 2.1370x; 1.4196x over previous
#include <cuda_runtime.h>
#include <math.h>

// Problem constants
#define NPTS   1048576
#define DH     256        // mlp_x hidden
#define R      64         // Tucker rank
#define HQ     128
#define HC     128
#define CIN    64
#define CORE_ELEMS (R*R*R)
#define NG     32            // quad point-groups per axis
#define G      256            // LUT grid per axis
#define GSHIFT 8

// ---------------- scratch (device globals) -------------
__device__ float g_up[2][NG][HQ];
__device__ float g_syp[2][NG];
__device__ float g_h[HC];
__device__ float g_v[R];
__device__ __align__(16) float g_w12[R * R];
__device__ float g_rpart[148][4];            // per-block {min0,max0,min1,max1}
__device__ float g_rangef[4];                // reduced {min0,max0,min1,max1}
__device__ __align__(16) float g_tbl[G * G]; // 256 KB LUT

// ---------------- helpers -------------
__device__ __forceinline__ float tanh_acc(float x) {
    float e, r;
    asm("ex2.approx.f32 %0, %1;" : "=f"(e) : "f"(x * 2.8853900817779268f));
    asm("rcp.approx.f32 %0, %1;" : "=f"(r) : "f"(e + 1.0f));
    return fmaf(-2.0f, r, 1.0f);
}
__device__ __forceinline__ float tanh_hw(float x) {
    float y;
    asm("tanh.approx.f32 %0, %1;" : "=f"(y) : "f"(x));
    return y;
}

// ---------------- K1: quad partial sums + core hidden + input min/max -------------
// blocks 0..63: quad (axis=b>>5, group=b&31); block 64: core hidden; 65..212: range.
__global__ void __launch_bounds__(256) k1(
    const float* __restrict__ qx0, const float* __restrict__ qx1,
    const float* __restrict__ eqp,
    const float* __restrict__ Wq01, const float* __restrict__ bq01,
    const float* __restrict__ Wq11, const float* __restrict__ bq11,
    const float* __restrict__ ci,   const float* __restrict__ Wc1,
    const float* __restrict__ bc1,
    const float4* __restrict__ inp4, int nf4)
{
    int b = blockIdx.x;
    int t = threadIdx.x;

    if (b >= 65) {           // ---- input bounding box (per-block, no atomics) ----
        __shared__ float rmin0[8], rmax0[8], rmin1[8], rmax1[8];
        int r = b - 65;
        float m0l = 1e30f, m0h = -1e30f, m1l = 1e30f, m1h = -1e30f;
        for (int i = r * 256 + t; i < nf4; i += 148 * 256) {
            float4 v = inp4[i];
            m0l = fminf(m0l, fminf(v.x, v.z));
            m0h = fmaxf(m0h, fmaxf(v.x, v.z));
            m1l = fminf(m1l, fminf(v.y, v.w));
            m1h = fmaxf(m1h, fmaxf(v.y, v.w));
        }
        #pragma unroll
        for (int o = 16; o; o >>= 1) {
            m0l = fminf(m0l, __shfl_xor_sync(0xffffffffu, m0l, o));
            m0h = fmaxf(m0h, __shfl_xor_sync(0xffffffffu, m0h, o));
            m1l = fminf(m1l, __shfl_xor_sync(0xffffffffu, m1l, o));
            m1h = fmaxf(m1h, __shfl_xor_sync(0xffffffffu, m1h, o));
        }
        if ((t & 31) == 0) {
            int w = t >> 5;
            rmin0[w] = m0l; rmax0[w] = m0h; rmin1[w] = m1l; rmax1[w] = m1h;
        }
        __syncthreads();
        if (t == 0) {
            float a0 = rmin0[0], b0 = rmax0[0], a1 = rmin1[0], b1 = rmax1[0];
            #pragma unroll
            for (int w = 1; w < 8; w++) {
                a0 = fminf(a0, rmin0[w]); b0 = fmaxf(b0, rmax0[w]);
                a1 = fminf(a1, rmin1[w]); b1 = fmaxf(b1, rmax1[w]);
            }
            g_rpart[r][0] = a0; g_rpart[r][1] = b0;
            g_rpart[r][2] = a1; g_rpart[r][3] = b1;
        }
        return;
    }

    if (b == 64) {           // ---- core hidden ----
        if (t < HC) {
            float z = bc1[t];
            #pragma unroll 8
            for (int i = 0; i < CIN; i++) z = fmaf(ci[i], Wc1[i * HC + t], z);
            g_h[t] = tanh_acc(z);
        }
        return;
    }

    int ax = b >> 5, g = b & 31;
    const float* qx = ax ? qx1 : qx0;
    const float* Wq = ax ? Wq11 : Wq01;
    const float* bq = ax ? bq11 : bq01;

    __shared__ float sx[32], sy[32], red[256];

    if (t < 32) {
        float x = qx[g * 32 + t];
        float y = sinf(3.14159265358979323846f * eqp[0] * x);
        sx[t] = x; sy[t] = y;
    }
    __syncthreads();

    int k = t & 127, sub = t >> 7;
    float W = Wq[k], bb = bq[k];
    float acc = 0.f;
    int c0 = sub * 16;
    #pragma unroll
    for (int c = 0; c < 16; c++) {
        float z = fmaf(sx[c0 + c], W, bb);
        acc = fmaf(sy[c0 + c], tanh_acc(z), acc);
    }
    red[t] = acc;
    __syncthreads();

    if (t < 128) g_up[ax][g][t] = red[t] + red[t + 128];
    else if (t < 160) {
        float s = sy[t - 128];
        #pragma unroll
        for (int o = 16; o; o >>= 1) s += __shfl_xor_sync(0xffffffffu, s, o);
        if (t == 128) g_syp[ax][g] = s;
    }
}

// ---------------- K1b: range reduce + zero g_v + compute w12 -> g_w12 -------------
__global__ void __launch_bounds__(256) k1b(
    const float* __restrict__ Wq02, const float* __restrict__ bq02,
    const float* __restrict__ Wq12, const float* __restrict__ bq12)
{
    __shared__ float su[2][HQ];
    __shared__ float s12[128];
    __shared__ float ssy[2];
    int t = threadIdx.x;

    // ---- range reduce: 4 warps, one component each ----
    if (t < 128) {
        int c = t >> 5, lane = t & 31;
        bool isMax = (c & 1);
        float m = isMax ? -1e30f : 1e30f;
        for (int i = lane; i < 148; i += 32) {
            float v = g_rpart[i][c];
            m = isMax ? fmaxf(m, v) : fminf(m, v);
        }
        #pragma unroll
        for (int o = 16; o; o >>= 1) {
            float s = __shfl_xor_sync(0xffffffffu, m, o);
            m = isMax ? fmaxf(m, s) : fminf(m, s);
        }
        if (lane == 0) g_rangef[c] = m;
    } else if (t < 192) {
        if (t - 128 < R) g_v[t - 128] = 0.f;   // reset atomic accumulator
    }

    {   // reduce partial u over 32 groups
        int ax = t >> 7, k = t & 127;
        float s0 = 0.f, s1 = 0.f, s2 = 0.f, s3 = 0.f;
        #pragma unroll
        for (int g = 0; g < NG; g += 4) {
            s0 += g_up[ax][g + 0][k];
            s1 += g_up[ax][g + 1][k];
            s2 += g_up[ax][g + 2][k];
            s3 += g_up[ax][g + 3][k];
        }
        su[ax][k] = (s0 + s1) + (s2 + s3);
    }
    if (t < 2) {
        float s = 0.f;
        #pragma unroll
        for (int g = 0; g < NG; g++) s += g_syp[t][g];
        ssy[t] = s;
    }
    __syncthreads();

    {
        int j = t & 127, sub = t >> 7;
        int ax = j >> 6, jj = j & 63;
        const float* W2 = ax ? Wq12 : Wq02;
        const float* b2 = ax ? bq12 : bq02;
        float s = sub ? 0.f : ssy[ax] * b2[jj];
        int k0 = sub * 64;
        #pragma unroll 8
        for (int k = 0; k < 64; k++) s = fmaf(su[ax][k0 + k], W2[(k0 + k) * R + jj], s);
        __shared__ float part[256];
        part[t] = s;
        __syncthreads();
        if (t < 128) s12[t] = part[t] + part[t + 128];
    }
    __syncthreads();

    #pragma unroll
    for (int i = t; i < R * R; i += 256)
        g_w12[i] = s12[i >> 6] * s12[64 + (i & 63)];
}

// ---------------- K2: streaming GEMV vs w12 (single wave: 7 blocks/SM) ----
__global__ void __launch_bounds__(256, 7) k2(
    const float* __restrict__ Wc2, const float* __restrict__ bc2)
{
    __shared__ __align__(16) float sw[R * R];   // 16 KB w12
    __shared__ float sred[8][8];
    int t = threadIdx.x;
    int h = blockIdx.x, ga = blockIdx.y;

    {
        const float4* src = (const float4*)g_w12;
        float4* dst = (float4*)sw;
        #pragma unroll
        for (int i = 0; i < 4; i++) dst[t + i * 256] = src[t + i * 256];
    }
    __syncthreads();

    const float* row  = (h < HC) ? (Wc2 + (size_t)h * CORE_ELEMS) : bc2;
    const float* base = row + (size_t)ga * 8 * (R * R);
    const float4* sw4 = (const float4*)sw;

    float acc[8] = {0.f, 0.f, 0.f, 0.f, 0.f, 0.f, 0.f, 0.f};

    #pragma unroll
    for (int i = 0; i < 4; i++) {
        const float4* p = (const float4*)base + t + i * 256;
        float4 ww = sw4[t + i * 256];
        // two half-batches of 4 independent LDG.128 (keeps regs under the 7-block cap)
        float4 c0 = p[0 * 1024], c1 = p[1 * 1024], c2 = p[2 * 1024], c3 = p[3 * 1024];
        acc[0] += fmaf(c0.x, ww.x, fmaf(c0.y, ww.y, fmaf(c0.z, ww.z, c0.w * ww.w)));
        acc[1] += fmaf(c1.x, ww.x, fmaf(c1.y, ww.y, fmaf(c1.z, ww.z, c1.w * ww.w)));
        acc[2] += fmaf(c2.x, ww.x, fmaf(c2.y, ww.y, fmaf(c2.z, ww.z, c2.w * ww.w)));
        acc[3] += fmaf(c3.x, ww.x, fmaf(c3.y, ww.y, fmaf(c3.z, ww.z, c3.w * ww.w)));
        float4 c4 = p[4 * 1024], c5 = p[5 * 1024], c6 = p[6 * 1024], c7 = p[7 * 1024];
        acc[4] += fmaf(c4.x, ww.x, fmaf(c4.y, ww.y, fmaf(c4.z, ww.z, c4.w * ww.w)));
        acc[5] += fmaf(c5.x, ww.x, fmaf(c5.y, ww.y, fmaf(c5.z, ww.z, c5.w * ww.w)));
        acc[6] += fmaf(c6.x, ww.x, fmaf(c6.y, ww.y, fmaf(c6.z, ww.z, c6.w * ww.w)));
        acc[7] += fmaf(c7.x, ww.x, fmaf(c7.y, ww.y, fmaf(c7.z, ww.z, c7.w * ww.w)));
    }

    #pragma unroll
    for (int aa = 0; aa < 8; aa++) {
        float s = acc[aa];
        #pragma unroll
        for (int o = 16; o; o >>= 1) s += __shfl_xor_sync(0xffffffffu, s, o);
        if ((t & 31) == 0) sred[aa][t >> 5] = s;
    }
    __syncthreads();
    if (t < 8) {
        float wh = (h < HC) ? g_h[h] : 1.0f;
        float s = 0.f;
        #pragma unroll
        for (int w = 0; w < 8; w++) s += sred[t][w];
        atomicAdd(&g_v[ga * 8 + t], wh * s);
    }
}

// ---------------- kB: build the GxG LUT -------------
__global__ void __launch_bounds__(256) kB(
    const float* __restrict__ Wx1, const float* __restrict__ bx1,
    const float* __restrict__ Wx2, const float* __restrict__ bx2)
{
    __shared__ __align__(16) float4 sw[DH];   // {w0, w1, b, w2v}
    __shared__ __align__(16) float sv[R];
    int t = threadIdx.x;

    if (t < R) sv[t] = g_v[t];
    __syncthreads();

    float w2v = 0.f, cc = 0.f;
    {
        const float4* wrow = (const float4*)(Wx2 + t * R);
        const float4* brow = (const float4*)bx2;
        const float4* v4   = (const float4*)sv;
        #pragma unroll
        for (int a = 0; a < R / 4; a++) {
            float4 w = wrow[a], b = brow[a], v = v4[a];
            w2v = fmaf(w.x, v.x, fmaf(w.y, v.y, fmaf(w.z, v.z, fmaf(w.w, v.w, w2v))));
            cc  = fmaf(b.x, v.x, fmaf(b.y, v.y, fmaf(b.z, v.z, fmaf(b.w, v.w, cc))));
        }
    }
    sw[t] = make_float4(Wx1[t], Wx1[DH + t], bx1[t], w2v);
    __syncthreads();

    float lo0 = g_rangef[0], hi0 = g_rangef[1];
    float lo1 = g_rangef[2], hi1 = g_rangef[3];
    float h0 = (hi0 - lo0) * (1.0f / (G - 1));
    float h1 = (hi1 - lo1) * (1.0f / (G - 1));

    int idx = blockIdx.x * 256 + t;
    int i = idx & (G - 1);
    int j = idx >> GSHIFT;
    float x0 = fmaf((float)i, h0, lo0);
    float x1 = fmaf((float)j, h1, lo1);

    float acc = cc;
    #pragma unroll 8
    for (int h = 0; h < DH; h++) {
        float4 w = sw[h];
        float z = fmaf(x0, w.x, fmaf(x1, w.y, w.z));
        acc = fmaf(tanh_hw(z), w.w, acc);
    }
    g_tbl[idx] = acc;
}

// ---------------- kI: bilinear interpolation of the LUT -------------
#define IPT 8
__global__ void __launch_bounds__(256) kI(
    const float2* __restrict__ inp, float* __restrict__ out, int n)
{
    __shared__ float sr[4];
    int t = threadIdx.x;
    if (t < 4) sr[t] = g_rangef[t];
    __syncthreads();
    float lo0 = sr[0], hi0 = sr[1], lo1 = sr[2], hi1 = sr[3];
    float inv0 = (hi0 > lo0) ? (float)(G - 1) / (hi0 - lo0) : 0.f;
    float inv1 = (hi1 > lo1) ? (float)(G - 1) / (hi1 - lo1) : 0.f;

    int base = blockIdx.x * (256 * IPT) + t;

    #pragma unroll
    for (int p = 0; p < IPT; p++) {
        int idx = base + p * 256;
        if (idx >= n) continue;
        float2 xy = inp[idx];
        float u = (xy.x - lo0) * inv0;
        float v = (xy.y - lo1) * inv1;
        int i = __float2int_rd(u);
        int j = __float2int_rd(v);
        i = min(max(i, 0), G - 2);
        j = min(max(j, 0), G - 2);
        float fu = u - (float)i;
        float fv = v - (float)j;
        const float* p0 = g_tbl + j * G + i;
        float t00 = __ldg(p0),     t01 = __ldg(p0 + 1);
        float t10 = __ldg(p0 + G), t11 = __ldg(p0 + G + 1);
        float a = fmaf(fu, t01 - t00, t00);
        float b = fmaf(fu, t11 - t10, t10);
        out[idx] = fmaf(fv, b - a, a);
    }
}

// ---------------- launch -------------
extern "C" void kernel_launch(void* const* d_in, const int* in_sizes, int n_in,
                              void* d_out, int out_size)
{
    const float* input  = (const float*)d_in[0];
    const float* eqp    = (const float*)d_in[1];
    const float* qx0    = (const float*)d_in[2];
    const float* qx1    = (const float*)d_in[3];
    const float* ci     = (const float*)d_in[4];
    const float* Wx1    = (const float*)d_in[5];
    const float* bx1    = (const float*)d_in[6];
    const float* Wx2    = (const float*)d_in[7];
    const float* bx2    = (const float*)d_in[8];
    const float* Wq01   = (const float*)d_in[9];
    const float* bq01   = (const float*)d_in[10];
    const float* Wq02   = (const float*)d_in[11];
    const float* bq02   = (const float*)d_in[12];
    const float* Wq11   = (const float*)d_in[13];
    const float* bq11   = (const float*)d_in[14];
    const float* Wq12   = (const float*)d_in[15];
    const float* bq12   = (const float*)d_in[16];
    const float* Wc1    = (const float*)d_in[17];
    const float* bc1    = (const float*)d_in[18];
    const float* Wc2    = (const float*)d_in[19];
    const float* bc2    = (const float*)d_in[20];

    int n = in_sizes[0] / 2;
    int nf4 = in_sizes[0] / 4;

    k1 <<<213, 256>>>(qx0, qx1, eqp, Wq01, bq01, Wq11, bq11, ci, Wc1, bc1,
                      (const float4*)input, nf4);
    k1b<<<1, 256>>>(Wq02, bq02, Wq12, bq12);
    k2 <<<dim3(129, 8), 256>>>(Wc2, bc2);
    kB <<<G * G / 256, 256>>>(Wx1, bx1, Wx2, bx2);
    kI <<<(n + 256 * IPT - 1) / (256 * IPT), 256>>>((const float2*)input, (float*)d_out, n);
}